// round 1
// baseline (speedup 1.0000x reference)
#include <cuda_runtime.h>
#include <math.h>

// Problem constants (from reference setup_inputs)
#define BATCH 8192
#define SDIM  70          // 64 sessions + 6 waitlist
#define NS    64
#define HID   1024
#define NACT  4096        // 4^6 actions, lexicographic product order
#define LOG_EPS (-20.723265836946407f)   // logf(1e-9f); feasible -> log(1+1e-9)==0 in fp32

// Scratch (allocation-free): hidden activations
__device__ float g_h1[BATCH * HID];
__device__ float g_h2[BATCH * HID];

// ---------------------------------------------------------------------------
// Tiled SGEMM: C[M,N] = act(A[M,K] @ B[K,N] + bias[N]),  row-major everywhere.
// Block tile 128x128, K-tile 8, 256 threads, 8x8 per-thread register tile.
// M, N are multiples of 128; K arbitrary (guarded).
// ---------------------------------------------------------------------------
template <int ACT>   // 0 = identity, 1 = tanh
__global__ __launch_bounds__(256, 2)
void sgemm_bias(const float* __restrict__ A, const float* __restrict__ B,
                const float* __restrict__ bias, float* __restrict__ C,
                int M, int N, int K)
{
    __shared__ float As[8][128];   // transposed: As[k][m]
    __shared__ float Bs[8][128];   // Bs[k][n]

    const int tid = threadIdx.x;
    const int bm  = blockIdx.y * 128;
    const int bn  = blockIdx.x * 128;
    const int tm  = (tid >> 4) * 8;   // 16 thread-rows
    const int tn  = (tid & 15) * 8;   // 16 thread-cols

    float acc[8][8];
#pragma unroll
    for (int i = 0; i < 8; i++)
#pragma unroll
        for (int j = 0; j < 8; j++) acc[i][j] = 0.0f;

    // Load mapping: 4 elements per thread per tile
    const int aM = (tid * 4) >> 3;   // A-tile row (0..127)
    const int aK = (tid * 4) & 7;    // A-tile k start (0 or 4)
    const int bK = (tid * 4) >> 7;   // B-tile k row (0..7)
    const int bN = (tid * 4) & 127;  // B-tile n start (multiple of 4)

    for (int k0 = 0; k0 < K; k0 += 8) {
        // A tile (scalar loads, guarded for K=70 tail)
#pragma unroll
        for (int i = 0; i < 4; i++) {
            int kk = aK + i;
            float v = 0.0f;
            if (k0 + kk < K) v = A[(size_t)(bm + aM) * K + k0 + kk];
            As[kk][aM] = v;
        }
        // B tile (vectorized; rows fully in/out of range per thread)
        if (k0 + bK < K) {
            float4 v = *reinterpret_cast<const float4*>(&B[(size_t)(k0 + bK) * N + bn + bN]);
            *reinterpret_cast<float4*>(&Bs[bK][bN]) = v;
        } else {
            *reinterpret_cast<float4*>(&Bs[bK][bN]) = make_float4(0.f, 0.f, 0.f, 0.f);
        }
        __syncthreads();

#pragma unroll
        for (int k = 0; k < 8; k++) {
            float a[8], b[8];
#pragma unroll
            for (int h = 0; h < 2; h++) {
                float4 t = *reinterpret_cast<const float4*>(&As[k][tm + h * 4]);
                a[h*4+0] = t.x; a[h*4+1] = t.y; a[h*4+2] = t.z; a[h*4+3] = t.w;
            }
#pragma unroll
            for (int h = 0; h < 2; h++) {
                float4 t = *reinterpret_cast<const float4*>(&Bs[k][tn + h * 4]);
                b[h*4+0] = t.x; b[h*4+1] = t.y; b[h*4+2] = t.z; b[h*4+3] = t.w;
            }
#pragma unroll
            for (int i = 0; i < 8; i++)
#pragma unroll
                for (int j = 0; j < 8; j++)
                    acc[i][j] = fmaf(a[i], b[j], acc[i][j]);
        }
        __syncthreads();
    }

    // Epilogue: bias (+ tanh), vectorized stores
#pragma unroll
    for (int i = 0; i < 8; i++) {
        float r[8];
#pragma unroll
        for (int j = 0; j < 8; j++) {
            float v = acc[i][j] + bias[bn + tn + j];
            if (ACT == 1) v = tanhf(v);
            r[j] = v;
        }
        float4* cp = reinterpret_cast<float4*>(&C[(size_t)(bm + tm + i) * N + bn + tn]);
        cp[0] = make_float4(r[0], r[1], r[2], r[3]);
        cp[1] = make_float4(r[4], r[5], r[6], r[7]);
    }
}

// ---------------------------------------------------------------------------
// In-place masked softmax over each row of logits [BATCH, NACT].
// Feasibility from base-4 digits of the action index vs floor(waitlist).
// One block (256 threads) per row; 16 elements per thread.
// ---------------------------------------------------------------------------
__global__ __launch_bounds__(256)
void masked_softmax(float* __restrict__ out, const float* __restrict__ states)
{
    const int row = blockIdx.x;
    const int tid = threadIdx.x;

    __shared__ float sred[32];
    __shared__ int   scap[6];

    if (tid < 6) {
        float w = states[(size_t)row * SDIM + NS + tid];
        scap[tid] = (int)floorf(w);   // w in [0,4): integer a <= w  <=>  a <= floor(w)
    }
    __syncthreads();

    const int c0 = scap[0], c1 = scap[1], c2 = scap[2];
    const int c3 = scap[3], c4 = scap[4], c5 = scap[5];

    float* rowp = out + (size_t)row * NACT;
    float vals[16];
    float mx = -INFINITY;

#pragma unroll
    for (int i = 0; i < 16; i++) {
        int a = tid + i * 256;
        float v = rowp[a];
        bool feas = (((a >> 10) & 3) <= c0) && (((a >> 8) & 3) <= c1) &&
                    (((a >> 6)  & 3) <= c2) && (((a >> 4) & 3) <= c3) &&
                    (((a >> 2)  & 3) <= c4) && (((a)      & 3) <= c5);
        if (!feas) v += LOG_EPS;
        vals[i] = v;
        mx = fmaxf(mx, v);
    }

    // Block max
#pragma unroll
    for (int o = 16; o > 0; o >>= 1) mx = fmaxf(mx, __shfl_xor_sync(0xffffffffu, mx, o));
    if ((tid & 31) == 0) sred[tid >> 5] = mx;
    __syncthreads();
    if (tid < 32) {
        float m = (tid < 8) ? sred[tid] : -INFINITY;
#pragma unroll
        for (int o = 4; o > 0; o >>= 1) m = fmaxf(m, __shfl_xor_sync(0xffffffffu, m, o));
        if (tid == 0) sred[0] = m;
    }
    __syncthreads();
    mx = sred[0];
    __syncthreads();   // sred reused below

    float sum = 0.0f;
#pragma unroll
    for (int i = 0; i < 16; i++) {
        vals[i] = expf(vals[i] - mx);
        sum += vals[i];
    }

    // Block sum
#pragma unroll
    for (int o = 16; o > 0; o >>= 1) sum += __shfl_xor_sync(0xffffffffu, sum, o);
    if ((tid & 31) == 0) sred[tid >> 5] = sum;
    __syncthreads();
    if (tid < 32) {
        float s = (tid < 8) ? sred[tid] : 0.0f;
#pragma unroll
        for (int o = 4; o > 0; o >>= 1) s += __shfl_xor_sync(0xffffffffu, s, o);
        if (tid == 0) sred[0] = s;
    }
    __syncthreads();
    const float inv = 1.0f / sred[0];

#pragma unroll
    for (int i = 0; i < 16; i++)
        rowp[tid + i * 256] = vals[i] * inv;
}

// ---------------------------------------------------------------------------
extern "C" void kernel_launch(void* const* d_in, const int* in_sizes, int n_in,
                              void* d_out, int out_size)
{
    const float* states = (const float*)d_in[0];
    const float* W1     = (const float*)d_in[1];
    const float* b1     = (const float*)d_in[2];
    const float* W2     = (const float*)d_in[3];
    const float* b2     = (const float*)d_in[4];
    const float* Wh     = (const float*)d_in[5];
    const float* bh     = (const float*)d_in[6];
    // d_in[7] = action_space (derived analytically), d_in[8] = num_sessions (compile-time)
    float* out = (float*)d_out;

    float* h1;  cudaGetSymbolAddress((void**)&h1, g_h1);
    float* h2;  cudaGetSymbolAddress((void**)&h2, g_h2);

    dim3 blk(256);
    // h1 = tanh(states @ W1 + b1)
    sgemm_bias<1><<<dim3(HID / 128, BATCH / 128), blk>>>(states, W1, b1, h1, BATCH, HID, SDIM);
    // h2 = tanh(h1 @ W2 + b2)
    sgemm_bias<1><<<dim3(HID / 128, BATCH / 128), blk>>>(h1, W2, b2, h2, BATCH, HID, HID);
    // logits = h2 @ Wh + bh   (written directly to d_out)
    sgemm_bias<0><<<dim3(NACT / 128, BATCH / 128), blk>>>(h2, Wh, bh, out, BATCH, NACT, HID);
    // in-place masked softmax
    masked_softmax<<<BATCH, blk>>>(out, states);
}

// round 3
// speedup vs baseline: 3.2350x; 3.2350x over previous
#include <cuda_runtime.h>
#include <cuda_bf16.h>
#include <math.h>
#include <stdint.h>

// Problem constants
#define BATCH 8192
#define SDIM  70
#define NS    64
#define HID   1024
#define NACT  4096
#define LOG_EPS (-20.723265836946407f)   // logf(1e-9f)

// ---------------------------------------------------------------------------
// Scratch (allocation-free __device__ globals)
// ---------------------------------------------------------------------------
__device__ __align__(16) __nv_bfloat16 g_h1h[BATCH * HID];
__device__ __align__(16) __nv_bfloat16 g_h1l[BATCH * HID];
__device__ __align__(16) __nv_bfloat16 g_h2h[BATCH * HID];
__device__ __align__(16) __nv_bfloat16 g_h2l[BATCH * HID];
__device__ __align__(16) __nv_bfloat16 g_W2Th[HID * HID];
__device__ __align__(16) __nv_bfloat16 g_W2Tl[HID * HID];
__device__ __align__(16) __nv_bfloat16 g_WhTh[NACT * HID];
__device__ __align__(16) __nv_bfloat16 g_WhTl[NACT * HID];

// ---------------------------------------------------------------------------
// Helpers (all plain sm_80+ PTX — no sm_103a-conditional instructions)
// ---------------------------------------------------------------------------
__device__ __forceinline__ uint32_t smem_u32(const void* p) {
    uint32_t a;
    asm("{ .reg .u64 t; cvta.to.shared.u64 t, %1; cvt.u32.u64 %0, t; }" : "=r"(a) : "l"(p));
    return a;
}

__device__ __forceinline__ void cp_async16(uint32_t saddr, const void* gaddr) {
    asm volatile("cp.async.cg.shared.global [%0], [%1], 16;" :: "r"(saddr), "l"(gaddr));
}
#define CP_COMMIT()  asm volatile("cp.async.commit_group;" ::: "memory")
#define CP_WAIT(n)   asm volatile("cp.async.wait_group %0;" :: "n"(n) : "memory")

__device__ __forceinline__ void ldsm_x4(uint32_t* r, uint32_t addr) {
    asm volatile("ldmatrix.sync.aligned.m8n8.x4.shared.b16 {%0,%1,%2,%3}, [%4];"
        : "=r"(r[0]), "=r"(r[1]), "=r"(r[2]), "=r"(r[3]) : "r"(addr));
}

__device__ __forceinline__ void mma16816(float* d, const uint32_t* a, const uint32_t* b) {
    asm volatile("mma.sync.aligned.m16n8k16.row.col.f32.bf16.bf16.f32 "
        "{%0,%1,%2,%3}, {%4,%5,%6,%7}, {%8,%9}, {%0,%1,%2,%3};"
        : "+f"(d[0]), "+f"(d[1]), "+f"(d[2]), "+f"(d[3])
        : "r"(a[0]), "r"(a[1]), "r"(a[2]), "r"(a[3]), "r"(b[0]), "r"(b[1]));
}

// ---------------------------------------------------------------------------
// HMMA GEMM:  C[M, Ntot] = act( A[M,K] @ B^T + bias ),  bf16 hi/lo split inputs
//   A as Ah/Al [M,K];  B as Bh/Bl [Ntot,K] (K-major).
//   Virtual K' = 3K:  seg0 Ah*Bh, seg1 Al*Bh, seg2 Ah*Bl.
//   OUT=0: fp32 (+bias) -> Cf. OUT=1: tanh(+bias) re-split bf16 -> Ch/Cl.
// CTA tile 128x128, K-tile 64, 8 warps (warp tile 32x64), 2-stage cp.async.
// Smem rows are 128B (64 bf16) with XOR-8 chunk swizzle: conflict-free
// ldmatrix reads and STS.128 writes.
// ---------------------------------------------------------------------------
#define KT 64
#define STAGE_BYTES 32768          // A 128x128B + B 128x128B
#define HMMA_SMEM (2 * STAGE_BYTES)

template <int OUT>
__global__ __launch_bounds__(256, 2)
void hmma_gemm(const __nv_bfloat16* __restrict__ Ah, const __nv_bfloat16* __restrict__ Al,
               const __nv_bfloat16* __restrict__ Bh, const __nv_bfloat16* __restrict__ Bl,
               const float* __restrict__ bias,
               float* __restrict__ Cf,
               __nv_bfloat16* __restrict__ Ch, __nv_bfloat16* __restrict__ Cl,
               int K, int Ntot)
{
    extern __shared__ char smem_raw[];
    const uint32_t sbase = smem_u32(smem_raw);

    const int tid  = threadIdx.x;
    const int lane = tid & 31;
    const int wid  = tid >> 5;
    const int wm   = wid & 3;          // 4 warps along M (32 rows each)
    const int wn   = wid >> 2;         // 2 warps along N (64 cols each)
    const int bm   = blockIdx.y * 128;
    const int bn   = blockIdx.x * 128;
    const int nst  = (3 * K) / KT;     // 48 for K=1024

    float acc[2][8][4];
#pragma unroll
    for (int i = 0; i < 2; i++)
#pragma unroll
        for (int j = 0; j < 8; j++)
#pragma unroll
            for (int q = 0; q < 4; q++) acc[i][j][q] = 0.0f;

    // ---- stage loader: 2048 16B chunks (A: 1024, B: 1024), 8 per thread ----
    auto load_stage = [&](int i, int s) {
        const int kk0 = i * KT;
        const int seg = kk0 / K;
        const int kl  = kk0 - seg * K;
        const __nv_bfloat16* Asrc = (seg == 1) ? Al : Ah;
        const __nv_bfloat16* Bsrc = (seg == 2) ? Bl : Bh;
        const uint32_t sA = sbase + s * STAGE_BYTES;
        const uint32_t sB = sA + 16384;
#pragma unroll
        for (int p = 0; p < 4; p++) {       // A tile
            const int idx = p * 256 + tid;
            const int r = idx >> 3, c = idx & 7;
            cp_async16(sA + r * 128 + ((c ^ (r & 7)) << 4),
                       Asrc + (size_t)(bm + r) * K + kl + c * 8);
        }
#pragma unroll
        for (int p = 0; p < 4; p++) {       // B tile
            const int idx = p * 256 + tid;
            const int r = idx >> 3, c = idx & 7;
            cp_async16(sB + r * 128 + ((c ^ (r & 7)) << 4),
                       Bsrc + (size_t)(bn + r) * K + kl + c * 8);
        }
        CP_COMMIT();
    };

    load_stage(0, 0);
    load_stage(1, 1);

    for (int i = 0; i < nst; i++) {
        const int s = i & 1;
        if (i + 1 < nst) { CP_WAIT(1); } else { CP_WAIT(0); }
        __syncthreads();

        const uint32_t sA = sbase + s * STAGE_BYTES;
        const uint32_t sB = sA + 16384;

#pragma unroll
        for (int ks = 0; ks < KT / 16; ks++) {
            // A fragments: 2 m16 tiles
            uint32_t a[2][4];
#pragma unroll
            for (int mt = 0; mt < 2; mt++) {
                const int row = wm * 32 + mt * 16 + (lane & 15);
                const int ch  = ks * 2 + (lane >> 4);
                ldsm_x4(a[mt], sA + row * 128 + ((ch ^ (row & 7)) << 4));
            }
            // B fragments: 4 x (ldmatrix.x4 covering 2 n8-tiles)
            uint32_t b[4][4];
#pragma unroll
            for (int np = 0; np < 4; np++) {
                const int nrow = wn * 64 + np * 16 + ((lane >> 4) << 3) + (lane & 7);
                const int ch   = ks * 2 + ((lane >> 3) & 1);
                ldsm_x4(b[np], sB + nrow * 128 + ((ch ^ (nrow & 7)) << 4));
            }
#pragma unroll
            for (int mt = 0; mt < 2; mt++)
#pragma unroll
                for (int np = 0; np < 4; np++) {
                    mma16816(acc[mt][np * 2 + 0], a[mt], &b[np][0]);
                    mma16816(acc[mt][np * 2 + 1], a[mt], &b[np][2]);
                }
        }
        __syncthreads();
        if (i + 2 < nst) load_stage(i + 2, s);
    }

    // ---- epilogue ----
    const int q  = lane & 3;
    const int r4 = lane >> 2;
#pragma unroll
    for (int mt = 0; mt < 2; mt++) {
#pragma unroll
        for (int nt = 0; nt < 8; nt++) {
            const int row0 = bm + wm * 32 + mt * 16 + r4;
            const int col  = bn + wn * 64 + nt * 8 + q * 2;
            const float b0 = bias[col], b1 = bias[col + 1];
            float d0 = acc[mt][nt][0] + b0;
            float d1 = acc[mt][nt][1] + b1;
            float d2 = acc[mt][nt][2] + b0;
            float d3 = acc[mt][nt][3] + b1;
            if (OUT == 0) {
                *reinterpret_cast<float2*>(Cf + (size_t)row0 * Ntot + col) =
                    make_float2(d0, d1);
                *reinterpret_cast<float2*>(Cf + (size_t)(row0 + 8) * Ntot + col) =
                    make_float2(d2, d3);
            } else {
                float t0 = tanhf(d0), t1 = tanhf(d1), t2 = tanhf(d2), t3 = tanhf(d3);
                __nv_bfloat16 h0 = __float2bfloat16(t0), h1 = __float2bfloat16(t1);
                __nv_bfloat16 h2 = __float2bfloat16(t2), h3 = __float2bfloat16(t3);
                __nv_bfloat162 hv01 = __nv_bfloat162(h0, h1);
                __nv_bfloat162 hv23 = __nv_bfloat162(h2, h3);
                __nv_bfloat162 lv01 = __nv_bfloat162(
                    __float2bfloat16(t0 - __bfloat162float(h0)),
                    __float2bfloat16(t1 - __bfloat162float(h1)));
                __nv_bfloat162 lv23 = __nv_bfloat162(
                    __float2bfloat16(t2 - __bfloat162float(h2)),
                    __float2bfloat16(t3 - __bfloat162float(h3)));
                *reinterpret_cast<__nv_bfloat162*>(Ch + (size_t)row0 * Ntot + col) = hv01;
                *reinterpret_cast<__nv_bfloat162*>(Ch + (size_t)(row0 + 8) * Ntot + col) = hv23;
                *reinterpret_cast<__nv_bfloat162*>(Cl + (size_t)row0 * Ntot + col) = lv01;
                *reinterpret_cast<__nv_bfloat162*>(Cl + (size_t)(row0 + 8) * Ntot + col) = lv23;
            }
        }
    }
}

// ---------------------------------------------------------------------------
// GEMM1 (fp32, K=70): h1 = tanh(states @ W1 + b1), split-stored as bf16 hi/lo
// ---------------------------------------------------------------------------
__global__ __launch_bounds__(256, 2)
void sgemm_split(const float* __restrict__ A, const float* __restrict__ B,
                 const float* __restrict__ bias,
                 __nv_bfloat16* __restrict__ Chh, __nv_bfloat16* __restrict__ Cll,
                 int M, int N, int K)
{
    __shared__ float As[8][128];
    __shared__ float Bs[8][128];

    const int tid = threadIdx.x;
    const int bm = blockIdx.y * 128, bn = blockIdx.x * 128;
    const int tm = (tid >> 4) * 8, tn = (tid & 15) * 8;

    float acc[8][8];
#pragma unroll
    for (int i = 0; i < 8; i++)
#pragma unroll
        for (int j = 0; j < 8; j++) acc[i][j] = 0.0f;

    const int aM = (tid * 4) >> 3, aK = (tid * 4) & 7;
    const int bK = (tid * 4) >> 7, bN = (tid * 4) & 127;

    for (int k0 = 0; k0 < K; k0 += 8) {
#pragma unroll
        for (int i = 0; i < 4; i++) {
            int kk = aK + i;
            float v = 0.0f;
            if (k0 + kk < K) v = A[(size_t)(bm + aM) * K + k0 + kk];
            As[kk][aM] = v;
        }
        if (k0 + bK < K)
            *reinterpret_cast<float4*>(&Bs[bK][bN]) =
                *reinterpret_cast<const float4*>(&B[(size_t)(k0 + bK) * N + bn + bN]);
        else
            *reinterpret_cast<float4*>(&Bs[bK][bN]) = make_float4(0.f, 0.f, 0.f, 0.f);
        __syncthreads();

#pragma unroll
        for (int k = 0; k < 8; k++) {
            float a[8], b[8];
#pragma unroll
            for (int h = 0; h < 2; h++) {
                float4 t = *reinterpret_cast<const float4*>(&As[k][tm + h * 4]);
                a[h*4] = t.x; a[h*4+1] = t.y; a[h*4+2] = t.z; a[h*4+3] = t.w;
            }
#pragma unroll
            for (int h = 0; h < 2; h++) {
                float4 t = *reinterpret_cast<const float4*>(&Bs[k][tn + h * 4]);
                b[h*4] = t.x; b[h*4+1] = t.y; b[h*4+2] = t.z; b[h*4+3] = t.w;
            }
#pragma unroll
            for (int i = 0; i < 8; i++)
#pragma unroll
                for (int j = 0; j < 8; j++)
                    acc[i][j] = fmaf(a[i], b[j], acc[i][j]);
        }
        __syncthreads();
    }

#pragma unroll
    for (int i = 0; i < 8; i++) {
        union { uint4 u; __nv_bfloat16 b[8]; } H, L;
#pragma unroll
        for (int j = 0; j < 8; j++) {
            float v = tanhf(acc[i][j] + bias[bn + tn + j]);
            __nv_bfloat16 hi = __float2bfloat16(v);
            H.b[j] = hi;
            L.b[j] = __float2bfloat16(v - __bfloat162float(hi));
        }
        *reinterpret_cast<uint4*>(&Chh[(size_t)(bm + tm + i) * N + bn + tn]) = H.u;
        *reinterpret_cast<uint4*>(&Cll[(size_t)(bm + tm + i) * N + bn + tn]) = L.u;
    }
}

// ---------------------------------------------------------------------------
// Weight prep: W[K,N] fp32 -> Wt_hi/Wt_lo [N,K] bf16 (transpose + split)
// ---------------------------------------------------------------------------
__global__ void transpose_split(const float* __restrict__ W,
                                __nv_bfloat16* __restrict__ Th,
                                __nv_bfloat16* __restrict__ Tl, int K, int N)
{
    __shared__ float t[32][33];
    const int k0 = blockIdx.x * 32, n0 = blockIdx.y * 32;
    const int tx = threadIdx.x, ty = threadIdx.y;
    for (int j = ty; j < 32; j += 8)
        t[j][tx] = W[(size_t)(k0 + j) * N + n0 + tx];
    __syncthreads();
    for (int j = ty; j < 32; j += 8) {
        float v = t[tx][j];
        __nv_bfloat16 hi = __float2bfloat16(v);
        Th[(size_t)(n0 + j) * K + k0 + tx] = hi;
        Tl[(size_t)(n0 + j) * K + k0 + tx] = __float2bfloat16(v - __bfloat162float(hi));
    }
}

// ---------------------------------------------------------------------------
// In-place masked softmax
// ---------------------------------------------------------------------------
__global__ __launch_bounds__(256)
void masked_softmax(float* __restrict__ out, const float* __restrict__ states)
{
    const int row = blockIdx.x;
    const int tid = threadIdx.x;

    __shared__ float sred[32];
    __shared__ int scap[6];

    if (tid < 6) scap[tid] = (int)floorf(states[(size_t)row * SDIM + NS + tid]);
    __syncthreads();

    const int c0 = scap[0], c1 = scap[1], c2 = scap[2];
    const int c3 = scap[3], c4 = scap[4], c5 = scap[5];

    float* rowp = out + (size_t)row * NACT;
    float vals[16];
    float mx = -INFINITY;

#pragma unroll
    for (int i = 0; i < 16; i++) {
        int a = tid + i * 256;
        float v = rowp[a];
        bool feas = (((a >> 10) & 3) <= c0) && (((a >> 8) & 3) <= c1) &&
                    (((a >> 6) & 3) <= c2) && (((a >> 4) & 3) <= c3) &&
                    (((a >> 2) & 3) <= c4) && (((a) & 3) <= c5);
        if (!feas) v += LOG_EPS;
        vals[i] = v;
        mx = fmaxf(mx, v);
    }

#pragma unroll
    for (int o = 16; o > 0; o >>= 1) mx = fmaxf(mx, __shfl_xor_sync(0xffffffffu, mx, o));
    if ((tid & 31) == 0) sred[tid >> 5] = mx;
    __syncthreads();
    if (tid < 32) {
        float m = (tid < 8) ? sred[tid] : -INFINITY;
#pragma unroll
        for (int o = 4; o > 0; o >>= 1) m = fmaxf(m, __shfl_xor_sync(0xffffffffu, m, o));
        if (tid == 0) sred[0] = m;
    }
    __syncthreads();
    mx = sred[0];
    __syncthreads();

    float sum = 0.0f;
#pragma unroll
    for (int i = 0; i < 16; i++) { vals[i] = expf(vals[i] - mx); sum += vals[i]; }

#pragma unroll
    for (int o = 16; o > 0; o >>= 1) sum += __shfl_xor_sync(0xffffffffu, sum, o);
    if ((tid & 31) == 0) sred[tid >> 5] = sum;
    __syncthreads();
    if (tid < 32) {
        float s = (tid < 8) ? sred[tid] : 0.0f;
#pragma unroll
        for (int o = 4; o > 0; o >>= 1) s += __shfl_xor_sync(0xffffffffu, s, o);
        if (tid == 0) sred[0] = s;
    }
    __syncthreads();
    const float inv = 1.0f / sred[0];

#pragma unroll
    for (int i = 0; i < 16; i++)
        rowp[tid + i * 256] = vals[i] * inv;
}

// ---------------------------------------------------------------------------
extern "C" void kernel_launch(void* const* d_in, const int* in_sizes, int n_in,
                              void* d_out, int out_size)
{
    const float* states = (const float*)d_in[0];
    const float* W1     = (const float*)d_in[1];
    const float* b1     = (const float*)d_in[2];
    const float* W2     = (const float*)d_in[3];
    const float* b2     = (const float*)d_in[4];
    const float* Wh     = (const float*)d_in[5];
    const float* bh     = (const float*)d_in[6];
    float* out = (float*)d_out;

    __nv_bfloat16 *h1h, *h1l, *h2h, *h2l, *W2Th, *W2Tl, *WhTh, *WhTl;
    cudaGetSymbolAddress((void**)&h1h,  g_h1h);
    cudaGetSymbolAddress((void**)&h1l,  g_h1l);
    cudaGetSymbolAddress((void**)&h2h,  g_h2h);
    cudaGetSymbolAddress((void**)&h2l,  g_h2l);
    cudaGetSymbolAddress((void**)&W2Th, g_W2Th);
    cudaGetSymbolAddress((void**)&W2Tl, g_W2Tl);
    cudaGetSymbolAddress((void**)&WhTh, g_WhTh);
    cudaGetSymbolAddress((void**)&WhTl, g_WhTl);

    cudaFuncSetAttribute(hmma_gemm<0>, cudaFuncAttributeMaxDynamicSharedMemorySize, HMMA_SMEM);
    cudaFuncSetAttribute(hmma_gemm<1>, cudaFuncAttributeMaxDynamicSharedMemorySize, HMMA_SMEM);

    // weight prep (transpose + bf16 split)
    transpose_split<<<dim3(HID / 32, HID / 32), dim3(32, 8)>>>(W2, W2Th, W2Tl, HID, HID);
    transpose_split<<<dim3(HID / 32, NACT / 32), dim3(32, 8)>>>(Wh, WhTh, WhTl, HID, NACT);

    // layer 1 (fp32 SGEMM, K=70) -> h1 split
    sgemm_split<<<dim3(HID / 128, BATCH / 128), 256>>>(states, W1, b1, h1h, h1l,
                                                       BATCH, HID, SDIM);
    // layer 2 (HMMA) -> h2 split
    hmma_gemm<1><<<dim3(HID / 128, BATCH / 128), 256, HMMA_SMEM>>>(
        h1h, h1l, W2Th, W2Tl, b2, nullptr, h2h, h2l, HID, HID);
    // head (HMMA) -> logits fp32 straight into d_out
    hmma_gemm<0><<<dim3(NACT / 128, BATCH / 128), 256, HMMA_SMEM>>>(
        h2h, h2l, WhTh, WhTl, bh, out, nullptr, nullptr, HID, NACT);
    // masked softmax in place
    masked_softmax<<<BATCH, 256>>>(out, states);
}